// round 1
// baseline (speedup 1.0000x reference)
#include <cuda_runtime.h>

// Quaternion tensor product:
//   view rows as 4 segments of 128 floats.
//   out[o][e] = sum over 16 paths coef * in0[s0][e] * in1[s1][e]
// which is exactly the Hamilton quaternion product per lane e:
//   o0 = a0*b0 - a1*b1 - a2*b2 - a3*b3
//   o1 = a0*b1 + a1*b0 + a2*b3 - a3*b2
//   o2 = a0*b2 - a1*b3 + a2*b0 + a3*b1
//   o3 = a0*b3 + a1*b2 - a2*b1 + a3*b0

#define EXTENT 128
#define NSEG 4
#define ROW (NSEG * EXTENT)          // 512 floats per row
#define GROUPS_PER_ROW (EXTENT / 4)  // 32 float4 groups per segment

__global__ void __launch_bounds__(256) quat_tp_kernel(
    const float* __restrict__ in0,
    const float* __restrict__ in1,
    float* __restrict__ out,
    long long total_groups)          // BATCH * GROUPS_PER_ROW
{
    long long g = (long long)blockIdx.x * blockDim.x + threadIdx.x;
    if (g >= total_groups) return;

    long long b = g >> 5;            // / GROUPS_PER_ROW
    int       l = (int)(g & 31);     // group within segment

    const float4* p0 = (const float4*)(in0 + b * ROW) + l;  // seg stride = 128 floats = 32 float4
    const float4* p1 = (const float4*)(in1 + b * ROW) + l;
    float4*       po = (float4*)(out + b * ROW) + l;

    // 8 independent 128-bit loads — maximize MLP
    float4 a0 = p0[0 * 32];
    float4 a1 = p0[1 * 32];
    float4 a2 = p0[2 * 32];
    float4 a3 = p0[3 * 32];
    float4 b0 = p1[0 * 32];
    float4 b1 = p1[1 * 32];
    float4 b2 = p1[2 * 32];
    float4 b3 = p1[3 * 32];

    float4 o0, o1, o2, o3;

    o0.x = a0.x*b0.x - a1.x*b1.x - a2.x*b2.x - a3.x*b3.x;
    o0.y = a0.y*b0.y - a1.y*b1.y - a2.y*b2.y - a3.y*b3.y;
    o0.z = a0.z*b0.z - a1.z*b1.z - a2.z*b2.z - a3.z*b3.z;
    o0.w = a0.w*b0.w - a1.w*b1.w - a2.w*b2.w - a3.w*b3.w;

    o1.x = a0.x*b1.x + a1.x*b0.x + a2.x*b3.x - a3.x*b2.x;
    o1.y = a0.y*b1.y + a1.y*b0.y + a2.y*b3.y - a3.y*b2.y;
    o1.z = a0.z*b1.z + a1.z*b0.z + a2.z*b3.z - a3.z*b2.z;
    o1.w = a0.w*b1.w + a1.w*b0.w + a2.w*b3.w - a3.w*b2.w;

    o2.x = a0.x*b2.x - a1.x*b3.x + a2.x*b0.x + a3.x*b1.x;
    o2.y = a0.y*b2.y - a1.y*b3.y + a2.y*b0.y + a3.y*b1.y;
    o2.z = a0.z*b2.z - a1.z*b3.z + a2.z*b0.z + a3.z*b1.z;
    o2.w = a0.w*b2.w - a1.w*b3.w + a2.w*b0.w + a3.w*b1.w;

    o3.x = a0.x*b3.x + a1.x*b2.x - a2.x*b1.x + a3.x*b0.x;
    o3.y = a0.y*b3.y + a1.y*b2.y - a2.y*b1.y + a3.y*b0.y;
    o3.z = a0.z*b3.z + a1.z*b2.z - a2.z*b1.z + a3.z*b0.z;
    o3.w = a0.w*b3.w + a1.w*b2.w - a2.w*b1.w + a3.w*b0.w;

    po[0 * 32] = o0;
    po[1 * 32] = o1;
    po[2 * 32] = o2;
    po[3 * 32] = o3;
}

extern "C" void kernel_launch(void* const* d_in, const int* in_sizes, int n_in,
                              void* d_out, int out_size) {
    const float* in0 = (const float*)d_in[0];
    const float* in1 = (const float*)d_in[1];
    float* out = (float*)d_out;

    long long batch = (long long)in_sizes[0] / ROW;
    long long total_groups = batch * GROUPS_PER_ROW;

    int threads = 256;
    long long blocks = (total_groups + threads - 1) / threads;
    quat_tp_kernel<<<(unsigned)blocks, threads>>>(in0, in1, out, total_groups);
}

// round 2
// speedup vs baseline: 1.0013x; 1.0013x over previous
#include <cuda_runtime.h>

// Quaternion tensor product (Hamilton product per lane):
//   o0 = a0*b0 - a1*b1 - a2*b2 - a3*b3
//   o1 = a0*b1 + a1*b0 + a2*b3 - a3*b2
//   o2 = a0*b2 - a1*b3 + a2*b0 + a3*b1
//   o3 = a0*b3 + a1*b2 - a2*b1 + a3*b0
// Pure streaming: 1.07 GB read + 0.54 GB write, zero reuse -> use .cs hints.

#define EXTENT 128
#define NSEG 4
#define ROW (NSEG * EXTENT)          // 512 floats per row
#define GROUPS_PER_ROW (EXTENT / 4)  // 32 float4 groups per segment

__global__ void __launch_bounds__(256) quat_tp_kernel(
    const float4* __restrict__ in0,
    const float4* __restrict__ in1,
    float4* __restrict__ out)
{
    // Grid is launched exactly: total_groups % blockDim == 0, no bounds check.
    long long g = (long long)blockIdx.x * blockDim.x + threadIdx.x;

    long long b = g >> 5;            // row index
    int       l = (int)(g & 31);     // float4 group within a segment

    const float4* p0 = in0 + b * (ROW / 4) + l;  // segment stride = 32 float4
    const float4* p1 = in1 + b * (ROW / 4) + l;
    float4*       po = out + b * (ROW / 4) + l;

    // 8 independent 128-bit streaming loads — evict-first in L1/L2
    float4 a0 = __ldcs(p0 + 0 * 32);
    float4 a1 = __ldcs(p0 + 1 * 32);
    float4 a2 = __ldcs(p0 + 2 * 32);
    float4 a3 = __ldcs(p0 + 3 * 32);
    float4 b0 = __ldcs(p1 + 0 * 32);
    float4 b1 = __ldcs(p1 + 1 * 32);
    float4 b2 = __ldcs(p1 + 2 * 32);
    float4 b3 = __ldcs(p1 + 3 * 32);

    float4 o0, o1, o2, o3;

    o0.x = a0.x*b0.x - a1.x*b1.x - a2.x*b2.x - a3.x*b3.x;
    o0.y = a0.y*b0.y - a1.y*b1.y - a2.y*b2.y - a3.y*b3.y;
    o0.z = a0.z*b0.z - a1.z*b1.z - a2.z*b2.z - a3.z*b3.z;
    o0.w = a0.w*b0.w - a1.w*b1.w - a2.w*b2.w - a3.w*b3.w;

    o1.x = a0.x*b1.x + a1.x*b0.x + a2.x*b3.x - a3.x*b2.x;
    o1.y = a0.y*b1.y + a1.y*b0.y + a2.y*b3.y - a3.y*b2.y;
    o1.z = a0.z*b1.z + a1.z*b0.z + a2.z*b3.z - a3.z*b2.z;
    o1.w = a0.w*b1.w + a1.w*b0.w + a2.w*b3.w - a3.w*b2.w;

    o2.x = a0.x*b2.x - a1.x*b3.x + a2.x*b0.x + a3.x*b1.x;
    o2.y = a0.y*b2.y - a1.y*b3.y + a2.y*b0.y + a3.y*b1.y;
    o2.z = a0.z*b2.z - a1.z*b3.z + a2.z*b0.z + a3.z*b1.z;
    o2.w = a0.w*b2.w - a1.w*b3.w + a2.w*b0.w + a3.w*b1.w;

    o3.x = a0.x*b3.x + a1.x*b2.x - a2.x*b1.x + a3.x*b0.x;
    o3.y = a0.y*b3.y + a1.y*b2.y - a2.y*b1.y + a3.y*b0.y;
    o3.z = a0.z*b3.z + a1.z*b2.z - a2.z*b1.z + a3.z*b0.z;
    o3.w = a0.w*b3.w + a1.w*b2.w - a2.w*b1.w + a3.w*b0.w;

    // Streaming stores — evict-first, no L2 retention
    __stcs(po + 0 * 32, o0);
    __stcs(po + 1 * 32, o1);
    __stcs(po + 2 * 32, o2);
    __stcs(po + 3 * 32, o3);
}

extern "C" void kernel_launch(void* const* d_in, const int* in_sizes, int n_in,
                              void* d_out, int out_size) {
    const float4* in0 = (const float4*)d_in[0];
    const float4* in1 = (const float4*)d_in[1];
    float4* out = (float4*)d_out;

    long long batch = (long long)in_sizes[0] / ROW;              // 262144
    long long total_groups = batch * GROUPS_PER_ROW;             // 8388608
    int threads = 256;
    long long blocks = (total_groups + threads - 1) / threads;   // exact: 32768
    quat_tp_kernel<<<(unsigned)blocks, threads>>>(in0, in1, out);
}

// round 4
// speedup vs baseline: 1.0087x; 1.0074x over previous
#include <cuda_runtime.h>

// Quaternion tensor product (Hamilton product per lane e):
//   o0 = a0*b0 - a1*b1 - a2*b2 - a3*b3
//   o1 = a0*b1 + a1*b0 + a2*b3 - a3*b2
//   o2 = a0*b2 - a1*b3 + a2*b0 + a3*b1
//   o3 = a0*b3 + a1*b2 - a2*b1 + a3*b0
// Pure streaming, zero reuse. 1.07 GB read + 0.54 GB write.
// This version uses 32-byte aligned aggregates so nvcc/ptxas can emit
// 256-bit LDG/STG on sm_103a (halves LSU ops, 256B loads in flight/thread).

#define EXTENT 128
#define NSEG 4
#define ROW_F4 (NSEG * EXTENT / 4)   // 128 float4 per row
#define SEG_F4 (EXTENT / 4)          // 32 float4 per segment
#define CHUNKS_PER_ROW (EXTENT / 8)  // 16 threads per row (8 lanes each)

struct __align__(32) F8 { float4 lo, hi; };

__device__ __forceinline__ float4 quat0(const float4&a0,const float4&a1,const float4&a2,const float4&a3,
                                        const float4&b0,const float4&b1,const float4&b2,const float4&b3){
    float4 o;
    o.x = a0.x*b0.x - a1.x*b1.x - a2.x*b2.x - a3.x*b3.x;
    o.y = a0.y*b0.y - a1.y*b1.y - a2.y*b2.y - a3.y*b3.y;
    o.z = a0.z*b0.z - a1.z*b1.z - a2.z*b2.z - a3.z*b3.z;
    o.w = a0.w*b0.w - a1.w*b1.w - a2.w*b2.w - a3.w*b3.w;
    return o;
}
__device__ __forceinline__ float4 quat1(const float4&a0,const float4&a1,const float4&a2,const float4&a3,
                                        const float4&b0,const float4&b1,const float4&b2,const float4&b3){
    float4 o;
    o.x = a0.x*b1.x + a1.x*b0.x + a2.x*b3.x - a3.x*b2.x;
    o.y = a0.y*b1.y + a1.y*b0.y + a2.y*b3.y - a3.y*b2.y;
    o.z = a0.z*b1.z + a1.z*b0.z + a2.z*b3.z - a3.z*b2.z;
    o.w = a0.w*b1.w + a1.w*b0.w + a2.w*b3.w - a3.w*b2.w;
    return o;
}
__device__ __forceinline__ float4 quat2(const float4&a0,const float4&a1,const float4&a2,const float4&a3,
                                        const float4&b0,const float4&b1,const float4&b2,const float4&b3){
    float4 o;
    o.x = a0.x*b2.x - a1.x*b3.x + a2.x*b0.x + a3.x*b1.x;
    o.y = a0.y*b2.y - a1.y*b3.y + a2.y*b0.y + a3.y*b1.y;
    o.z = a0.z*b2.z - a1.z*b3.z + a2.z*b0.z + a3.z*b1.z;
    o.w = a0.w*b2.w - a1.w*b3.w + a2.w*b0.w + a3.w*b1.w;
    return o;
}
__device__ __forceinline__ float4 quat3(const float4&a0,const float4&a1,const float4&a2,const float4&a3,
                                        const float4&b0,const float4&b1,const float4&b2,const float4&b3){
    float4 o;
    o.x = a0.x*b3.x + a1.x*b2.x - a2.x*b1.x + a3.x*b0.x;
    o.y = a0.y*b3.y + a1.y*b2.y - a2.y*b1.y + a3.y*b0.y;
    o.z = a0.z*b3.z + a1.z*b2.z - a2.z*b1.z + a3.z*b0.z;
    o.w = a0.w*b3.w + a1.w*b2.w - a2.w*b1.w + a3.w*b0.w;
    return o;
}

__global__ void __launch_bounds__(256) quat_tp_kernel(
    const F8* __restrict__ in0,
    const F8* __restrict__ in1,
    F8* __restrict__ out)
{
    // One thread = 8 consecutive lanes of one row. 16 threads per row.
    // Grid launched exactly; no bounds check.
    long long g = (long long)blockIdx.x * blockDim.x + threadIdx.x;
    long long b = g >> 4;            // row index
    int       t = (int)(g & 15);     // 32B chunk within a segment

    // F8 units: row = 64 F8, segment = 16 F8
    const F8* p0 = in0 + b * 64 + t;
    const F8* p1 = in1 + b * 64 + t;
    F8*       po = out + b * 64 + t;

    // 8 independent 256-bit loads per operand slot (16 total, 512 B in flight)
    F8 a0 = p0[0 * 16];
    F8 a1 = p0[1 * 16];
    F8 a2 = p0[2 * 16];
    F8 a3 = p0[3 * 16];
    F8 b0 = p1[0 * 16];
    F8 b1 = p1[1 * 16];
    F8 b2 = p1[2 * 16];
    F8 b3 = p1[3 * 16];

    F8 o0, o1, o2, o3;
    o0.lo = quat0(a0.lo,a1.lo,a2.lo,a3.lo, b0.lo,b1.lo,b2.lo,b3.lo);
    o0.hi = quat0(a0.hi,a1.hi,a2.hi,a3.hi, b0.hi,b1.hi,b2.hi,b3.hi);
    o1.lo = quat1(a0.lo,a1.lo,a2.lo,a3.lo, b0.lo,b1.lo,b2.lo,b3.lo);
    o1.hi = quat1(a0.hi,a1.hi,a2.hi,a3.hi, b0.hi,b1.hi,b2.hi,b3.hi);
    o2.lo = quat2(a0.lo,a1.lo,a2.lo,a3.lo, b0.lo,b1.lo,b2.lo,b3.lo);
    o2.hi = quat2(a0.hi,a1.hi,a2.hi,a3.hi, b0.hi,b1.hi,b2.hi,b3.hi);
    o3.lo = quat3(a0.lo,a1.lo,a2.lo,a3.lo, b0.lo,b1.lo,b2.lo,b3.lo);
    o3.hi = quat3(a0.hi,a1.hi,a2.hi,a3.hi, b0.hi,b1.hi,b2.hi,b3.hi);

    po[0 * 16] = o0;
    po[1 * 16] = o1;
    po[2 * 16] = o2;
    po[3 * 16] = o3;
}

extern "C" void kernel_launch(void* const* d_in, const int* in_sizes, int n_in,
                              void* d_out, int out_size) {
    const F8* in0 = (const F8*)d_in[0];
    const F8* in1 = (const F8*)d_in[1];
    F8* out = (F8*)d_out;

    long long batch = (long long)in_sizes[0] / (NSEG * EXTENT);   // 262144
    long long total_threads = batch * CHUNKS_PER_ROW;             // 4194304
    int threads = 256;
    long long blocks = (total_threads + threads - 1) / threads;   // exact: 16384
    quat_tp_kernel<<<(unsigned)blocks, threads>>>(in0, in1, out);
}